// round 16
// baseline (speedup 1.0000x reference)
#include <cuda_runtime.h>
#include <cstdint>
#include <cstddef>

// ---------------------------------------------------------------------------
// NTM single step.  B=256, N=2048, M=64, CS=512, INP=256, OUT=256
// ---------------------------------------------------------------------------

#define Bb 256
#define Nn 2048
#define Mm 64
#define CS 512
#define KG 832      // INP + M + CS
#define NG 2048     // 4*CS
#define NRW 268     // ADDR_R(70) + ADDR_W(198)
#define KO 576      // CS + M

// output offsets (elements)
#define OFF_OUT 0
#define OFF_MEM 65536
#define OFF_H   33619968
#define OFF_C   33751040
#define OFF_WR  33882112
#define OFF_WW  34406400
#define OFF_RV  34930688

// scratch (all GEMM operands pre-rounded to tf32 by producers)
__device__ float g_A1[Bb * KG];
__device__ float g_Wg[NG * KG];
__device__ float g_gates[Bb * NG];
__device__ float g_Wrw[NRW * CS];
__device__ float g_rw[Bb * NRW];
__device__ float g_A2[Bb * KO];
__device__ float g_Wo[256 * KO];
__device__ float g_h32[Bb * CS];

__device__ __forceinline__ float sigm(float x) { return 1.f / (1.f + __expf(-x)); }
__device__ __forceinline__ float ftanh(float x) {
    float e = __expf(2.f * x);
    return (e - 1.f) / (e + 1.f);
}
__device__ __forceinline__ float softplus(float x) { return x > 20.f ? x : log1pf(expf(x)); }
__device__ __forceinline__ float to_tf32(float x) {
    float r; asm("cvt.rna.tf32.f32 %0, %1;" : "=f"(r) : "f"(x)); return r;
}
__device__ __forceinline__ float4 r4(float4 v) {
    return make_float4(to_tf32(v.x), to_tf32(v.y), to_tf32(v.z), to_tf32(v.w));
}

// ------------------------- combined prep (float4, tf32-rounded) --------------

__global__ void prep_all(const float4* __restrict__ Wih, const float4* __restrict__ Whh,
                         const float* __restrict__ bih, const float* __restrict__ bhh,
                         const float4* __restrict__ Wr,  const float* __restrict__ br,
                         const float4* __restrict__ Ww,  const float* __restrict__ bw,
                         const float4* __restrict__ x,   const float4* __restrict__ prev_read,
                         const float4* __restrict__ h,   const float4* __restrict__ Wo,
                         const float* __restrict__ bo,   float* __restrict__ o_out) {
    int idx = blockIdx.x * blockDim.x + threadIdx.x;
    if (idx < NG * 208) {
        int n = idx / 208, f = idx - n * 208;
        ((float4*)g_Wg)[idx] = r4((f < 80) ? Wih[n * 80 + f] : Whh[n * 128 + (f - 80)]);
    }
    if (idx < Bb * NG) {
        int j = idx & (NG - 1);
        g_gates[idx] = bih[j] + bhh[j];
    }
    if (idx < NRW * 128) {
        int r = idx >> 7, f = idx & 127;
        ((float4*)g_Wrw)[idx] = r4((r < 70) ? Wr[idx] : Ww[(r - 70) * 128 + f]);
    }
    if (idx < Bb * NRW) {
        int j = idx % NRW;
        g_rw[idx] = (j < 70) ? br[j] : bw[j - 70];
    }
    if (idx < Bb * 256) {
        o_out[idx] = bo[idx & 255];
    }
    if (idx < Bb * 208) {
        int b = idx / 208, f = idx - b * 208;
        float4 v;
        if (f < 64)      v = x[b * 64 + f];
        else if (f < 80) v = prev_read[b * 16 + (f - 64)];
        else             v = h[b * 128 + (f - 80)];
        ((float4*)g_A1)[idx] = r4(v);
    }
    if (idx < 256 * 144) {
        ((float4*)g_Wo)[idx] = r4(Wo[idx]);
    }
}

// ------------------------- tf32 tensor-core GEMM (bulk-round, split-K) -------
// C += A[M,K] @ W[N,K]^T over [z*Ksub, (z+1)*Ksub), atomic epilogue.
// Processes K in ROUNDS of up to 4 tiles: one cp.async commit + ONE wait per
// round (instead of one L2 round-trip per 16-wide tile).  C pre-init w/ bias.

#define STAGE_BYTES 5120   // 64*20*4

__device__ __forceinline__ void mma_tf32(float* c, const uint32_t* a,
                                         uint32_t b0, uint32_t b1) {
    asm volatile(
        "mma.sync.aligned.m16n8k8.row.col.f32.tf32.tf32.f32 "
        "{%0,%1,%2,%3}, {%4,%5,%6,%7}, {%8,%9}, {%0,%1,%2,%3};\n"
        : "+f"(c[0]), "+f"(c[1]), "+f"(c[2]), "+f"(c[3])
        : "r"(a[0]), "r"(a[1]), "r"(a[2]), "r"(a[3]), "r"(b0), "r"(b1));
}

__device__ __forceinline__ void cp16(uint32_t dst, const float* src, int sz) {
    asm volatile("cp.async.ca.shared.global [%0], [%1], 16, %2;\n"
                 :: "r"(dst), "l"(src), "r"(sz));
}

__global__ void __launch_bounds__(256, 2)
gemm_tf32(const float* __restrict__ A, const float* __restrict__ W,
          float* __restrict__ C, int M, int N, int K, int Ksub) {
    __shared__ float As[4][64][20];
    __shared__ float Bs[4][64][20];
    int bm = blockIdx.y * 64, bn = blockIdx.x * 64;
    int kOff = blockIdx.z * Ksub;
    int tid = threadIdx.x;
    int wid = tid >> 5, lane = tid & 31;
    int wm = (wid & 1) * 32, wn = (wid >> 1) * 16;
    int gid = lane >> 2, tig = lane & 3;

    int r = tid >> 2;
    int c4 = (tid & 3) << 2;
    const float* Ap = A + (size_t)(bm + r) * K + kOff + c4;
    bool wvalid = (bn + r) < N;
    int wsz = wvalid ? 16 : 0;
    const float* Wp = W + (size_t)(wvalid ? (bn + r) : 0) * K + kOff + c4;

    uint32_t aDst = (uint32_t)__cvta_generic_to_shared(&As[0][r][c4]);
    uint32_t bDst = (uint32_t)__cvta_generic_to_shared(&Bs[0][r][c4]);

    float acc[2][2][4];
#pragma unroll
    for (int i = 0; i < 2; i++)
#pragma unroll
        for (int j = 0; j < 2; j++)
#pragma unroll
            for (int q = 0; q < 4; q++) acc[i][j][q] = 0.f;

    int numK = Ksub >> 4;

    for (int base = 0; base < numK; base += 4) {
        int cnt = (numK - base < 4) ? (numK - base) : 4;
        // issue the whole round's tiles, ONE commit + ONE wait
#pragma unroll
        for (int s = 0; s < 4; s++) {
            if (s < cnt) {
                cp16(aDst + s * STAGE_BYTES, Ap + (base + s) * 16, 16);
                cp16(bDst + s * STAGE_BYTES, Wp + (base + s) * 16, wsz);
            }
        }
        asm volatile("cp.async.commit_group;\n");
        asm volatile("cp.async.wait_group 0;\n");
        __syncthreads();

#pragma unroll
        for (int st = 0; st < 4; st++) {
            if (st >= cnt) break;
#pragma unroll
            for (int kk = 0; kk < 16; kk += 8) {
                uint32_t af[2][4];
#pragma unroll
                for (int i = 0; i < 2; i++) {
                    int r0 = wm + i * 16 + gid;
                    af[i][0] = __float_as_uint(As[st][r0][kk + tig]);
                    af[i][1] = __float_as_uint(As[st][r0 + 8][kk + tig]);
                    af[i][2] = __float_as_uint(As[st][r0][kk + tig + 4]);
                    af[i][3] = __float_as_uint(As[st][r0 + 8][kk + tig + 4]);
                }
#pragma unroll
                for (int j = 0; j < 2; j++) {
                    int c0 = wn + j * 8 + gid;
                    uint32_t b0 = __float_as_uint(Bs[st][c0][kk + tig]);
                    uint32_t b1 = __float_as_uint(Bs[st][c0][kk + tig + 4]);
#pragma unroll
                    for (int i = 0; i < 2; i++) mma_tf32(acc[i][j], af[i], b0, b1);
                }
            }
        }
        __syncthreads();   // protect smem before next round's overwrite
    }

#pragma unroll
    for (int i = 0; i < 2; i++) {
        int row = bm + wm + i * 16 + gid;
#pragma unroll
        for (int j = 0; j < 2; j++) {
            int col = bn + wn + j * 8 + tig * 2;
            if (col < N) {
                atomicAdd(&C[(size_t)row * N + col],           acc[i][j][0]);
                atomicAdd(&C[(size_t)row * N + col + 1],       acc[i][j][1]);
                atomicAdd(&C[(size_t)(row + 8) * N + col],     acc[i][j][2]);
                atomicAdd(&C[(size_t)(row + 8) * N + col + 1], acc[i][j][3]);
            }
        }
    }
}

// ------------------------- LSTM pointwise (scalar, high-occupancy) -----------

__global__ void lstm_pw(const float* __restrict__ c_in,
                        float* __restrict__ h_out, float* __restrict__ c_out) {
    int idx = blockIdx.x * blockDim.x + threadIdx.x;
    if (idx >= Bb * CS) return;
    int b = idx >> 9, j = idx & 511;
    const float* g = g_gates + (size_t)b * NG;
    float ig = sigm(g[j]);
    float fg = sigm(g[512 + j]);
    float gg = ftanh(g[1024 + j]);
    float og = sigm(g[1536 + j]);
    float cn = fg * c_in[idx] + ig * gg;
    float hn = og * ftanh(cn);
    c_out[idx] = cn;
    h_out[idx] = hn;
    g_h32[idx] = to_tf32(hn);
}

// ------------------------- block reductions (512 threads, 16 warps) ----------

__device__ __forceinline__ float bred_max(float v, float* s16) {
#pragma unroll
    for (int off = 16; off; off >>= 1)
        v = fmaxf(v, __shfl_xor_sync(0xffffffffu, v, off));
    int wid = threadIdx.x >> 5, lane = threadIdx.x & 31;
    if (lane == 0) s16[wid] = v;
    __syncthreads();
    if (wid == 0) {
        float x = (lane < 16) ? s16[lane] : -1e30f;
#pragma unroll
        for (int off = 8; off; off >>= 1)
            x = fmaxf(x, __shfl_xor_sync(0xffffffffu, x, off));
        if (lane == 0) s16[0] = x;
    }
    __syncthreads();
    float r = s16[0];
    __syncthreads();
    return r;
}

__device__ __forceinline__ float bred_sum(float v, float* s16) {
#pragma unroll
    for (int off = 16; off; off >>= 1)
        v += __shfl_xor_sync(0xffffffffu, v, off);
    int wid = threadIdx.x >> 5, lane = threadIdx.x & 31;
    if (lane == 0) s16[wid] = v;
    __syncthreads();
    if (wid == 0) {
        float x = (lane < 16) ? s16[lane] : 0.f;
#pragma unroll
        for (int off = 8; off; off >>= 1)
            x += __shfl_xor_sync(0xffffffffu, x, off);
        if (lane == 0) s16[0] = x;
    }
    __syncthreads();
    float r = s16[0];
    __syncthreads();
    return r;
}

// ------------------------- fused memory pass ---------------------------------
// One CTA per batch element (grid=256, block=512).

__global__ void __launch_bounds__(512, 2)
fused_mem(const float* __restrict__ mem,
          const float* __restrict__ read_w_prev,
          const float* __restrict__ write_w_prev,
          float* __restrict__ mem_out,
          float* __restrict__ w_read_out,
          float* __restrict__ w_write_out,
          float* __restrict__ read_vec) {
    __shared__ float s_simr[Nn], s_simw[Nn], s_wg[Nn];
    __shared__ float s_kr[64], s_kw[64], s_er[64], s_ad[64];
    __shared__ float s_par[2][6];
    __shared__ float s_nrm[2];
    __shared__ float s_red[16];

    int b = blockIdx.x;
    int t = threadIdx.x;
    const float* base = g_rw + (size_t)b * NRW;

    if (t < 64)        s_kr[t] = base[t];
    else if (t < 128)  s_kw[t - 64] = base[70 + (t - 64)];
    else if (t < 192)  s_er[t - 128] = sigm(base[140 + (t - 128)]);
    else if (t < 256)  s_ad[t - 192] = base[204 + (t - 192)];
    else if (t < 258) {
        int head = t - 256;
        const float* ov = base + head * 70;
        float beta = softplus(ov[64]);
        float gg = sigm(ov[65]);
        float s0 = ov[66], s1 = ov[67], s2 = ov[68];
        float sm = fmaxf(s0, fmaxf(s1, s2));
        float e0 = __expf(s0 - sm), e1 = __expf(s1 - sm), e2 = __expf(s2 - sm);
        float es = e0 + e1 + e2;
        s_par[head][0] = beta; s_par[head][1] = gg;
        s_par[head][2] = e0 / es; s_par[head][3] = e1 / es; s_par[head][4] = e2 / es;
        s_par[head][5] = 1.f + softplus(ov[69]);
    }
    __syncthreads();

    int wid = t >> 5, lane = t & 31;
    if (wid < 2) {
        const float* k = wid ? s_kw : s_kr;
        float s = k[lane] * k[lane] + k[lane + 32] * k[lane + 32];
#pragma unroll
        for (int off = 16; off; off >>= 1) s += __shfl_xor_sync(0xffffffffu, s, off);
        if (lane == 0) s_nrm[wid] = sqrtf(s) + 1e-8f;
    }
    __syncthreads();

    int g = t >> 3, l = t & 7;
    float krf[8], kwf[8], erf[8], adf[8];
#pragma unroll
    for (int j = 0; j < 8; j++) {
        krf[j] = s_kr[l * 8 + j]; kwf[j] = s_kw[l * 8 + j];
        erf[j] = s_er[l * 8 + j]; adf[j] = s_ad[l * 8 + j];
    }
    float nrmr = s_nrm[0], nrmw = s_nrm[1];

    const float* mrow = mem + ((size_t)b * Nn) * 64 + l * 8;

    // pass 1: similarity (unroll 4 -> 8 LDG.128 in flight per thread)
#pragma unroll 4
    for (int i = 0; i < 32; i++) {
        int n = i * 64 + g;
        const float* p = mrow + (size_t)n * 64;
        float4 m0 = *(const float4*)p;
        float4 m1 = *(const float4*)(p + 4);
        float m[8] = {m0.x, m0.y, m0.z, m0.w, m1.x, m1.y, m1.z, m1.w};
        float dr = 0.f, dw = 0.f, sq = 0.f;
#pragma unroll
        for (int j = 0; j < 8; j++) {
            dr += m[j] * krf[j]; dw += m[j] * kwf[j]; sq += m[j] * m[j];
        }
#pragma unroll
        for (int off = 4; off; off >>= 1) {
            dr += __shfl_xor_sync(0xffffffffu, dr, off);
            dw += __shfl_xor_sync(0xffffffffu, dw, off);
            sq += __shfl_xor_sync(0xffffffffu, sq, off);
        }
        if (l == 0) {
            float nm = sqrtf(sq) + 1e-8f;
            s_simr[n] = dr / (nrmr * nm);
            s_simw[n] = dw / (nrmw * nm);
        }
    }
    __syncthreads();

    // phase 2: addressing, both heads
    for (int head = 0; head < 2; head++) {
        float* sim = head ? s_simw : s_simr;
        const float* prevg = (head ? write_w_prev : read_w_prev) + (size_t)b * Nn;
        float* wout = (head ? w_write_out : w_read_out) + (size_t)b * Nn;
        float beta = s_par[head][0], gg = s_par[head][1];
        float e0 = s_par[head][2], e1 = s_par[head][3], e2 = s_par[head][4];
        float gamma = s_par[head][5];

        float loc[4];
        float mx = -1e30f;
#pragma unroll
        for (int i = 0; i < 4; i++) {
            float v = beta * sim[t + i * 512];
            loc[i] = v;
            mx = fmaxf(mx, v);
        }
        mx = bred_max(mx, s_red);
        float sum = 0.f;
#pragma unroll
        for (int i = 0; i < 4; i++) { loc[i] = __expf(loc[i] - mx); sum += loc[i]; }
        sum = bred_sum(sum, s_red);
        float inv = 1.f / sum;
#pragma unroll
        for (int i = 0; i < 4; i++) {
            int n = t + i * 512;
            s_wg[n] = gg * loc[i] * inv + (1.f - gg) * prevg[n];
        }
        __syncthreads();
        float ws[4];
        float sum2 = 0.f;
#pragma unroll
        for (int i = 0; i < 4; i++) {
            int n = t + i * 512;
            float v = e0 * s_wg[(n + Nn - 1) & (Nn - 1)] + e1 * s_wg[n]
                    + e2 * s_wg[(n + 1) & (Nn - 1)];
            v = __powf(v, gamma);
            ws[i] = v;
            sum2 += v;
        }
        sum2 = bred_sum(sum2, s_red);
        float inv2 = 1.f / (sum2 + 1e-8f);
#pragma unroll
        for (int i = 0; i < 4; i++) {
            int n = t + i * 512;
            float w = ws[i] * inv2;
            wout[n] = w;
            sim[n] = w;
        }
        __syncthreads();
    }

    // pass 3: memory update + read_vec (reverse order, streaming hints)
    float rv[8];
#pragma unroll
    for (int j = 0; j < 8; j++) rv[j] = 0.f;
    float* orow = mem_out + ((size_t)b * Nn) * 64 + l * 8;
#pragma unroll 4
    for (int i = 31; i >= 0; i--) {
        int n = i * 64 + g;
        float wr = s_simr[n], ww = s_simw[n];
        const float* p = mrow + (size_t)n * 64;
        float4 m0 = __ldcs((const float4*)p);
        float4 m1 = __ldcs((const float4*)(p + 4));
        float m[8] = {m0.x, m0.y, m0.z, m0.w, m1.x, m1.y, m1.z, m1.w};
        float o[8];
#pragma unroll
        for (int j = 0; j < 8; j++) {
            o[j] = m[j] * (1.f - ww * erf[j]) + ww * adf[j];
            rv[j] += wr * m[j];
        }
        float* q = orow + (size_t)n * 64;
        __stcs((float4*)q,       make_float4(o[0], o[1], o[2], o[3]));
        __stcs((float4*)(q + 4), make_float4(o[4], o[5], o[6], o[7]));
    }
    __syncthreads();

    float* part = (g < 32) ? &s_simr[g * 64] : &s_simw[(g - 32) * 64];
#pragma unroll
    for (int j = 0; j < 8; j++) part[l * 8 + j] = rv[j];
    g_A2[(size_t)b * KO + t] = g_h32[(size_t)b * CS + t];
    __syncthreads();
    if (t < 64) {
        float s = 0.f;
#pragma unroll 8
        for (int g2 = 0; g2 < 32; g2++) s += s_simr[g2 * 64 + t];
#pragma unroll 8
        for (int g2 = 0; g2 < 32; g2++) s += s_simw[g2 * 64 + t];
        read_vec[(size_t)b * Mm + t] = s;
        g_A2[(size_t)b * KO + CS + t] = to_tf32(s);
    }
}

// ---------------------------------------------------------------------------

extern "C" void kernel_launch(void* const* d_in, const int* in_sizes, int n_in,
                              void* d_out, int out_size) {
    const float* x         = (const float*)d_in[0];
    const float* memory    = (const float*)d_in[1];
    const float* h         = (const float*)d_in[2];
    const float* c         = (const float*)d_in[3];
    const float* read_w    = (const float*)d_in[4];
    const float* write_w   = (const float*)d_in[5];
    const float* prev_read = (const float*)d_in[6];
    const float* W_ih      = (const float*)d_in[7];
    const float* W_hh      = (const float*)d_in[8];
    const float* b_ih      = (const float*)d_in[9];
    const float* b_hh      = (const float*)d_in[10];
    const float* W_r       = (const float*)d_in[11];
    const float* b_r       = (const float*)d_in[12];
    const float* W_w       = (const float*)d_in[13];
    const float* b_w       = (const float*)d_in[14];
    const float* W_o       = (const float*)d_in[15];
    const float* b_o       = (const float*)d_in[16];

    float* out  = (float*)d_out;
    float* o_out = out + OFF_OUT;
    float* o_mem = out + OFF_MEM;
    float* o_h   = out + OFF_H;
    float* o_c   = out + OFF_C;
    float* o_wr  = out + OFF_WR;
    float* o_ww  = out + OFF_WW;
    float* o_rv  = out + OFF_RV;

    float *A1, *Wg, *gates, *Wrw, *A2, *rw, *Wo, *h32;
    cudaGetSymbolAddress((void**)&A1,    g_A1);
    cudaGetSymbolAddress((void**)&Wg,    g_Wg);
    cudaGetSymbolAddress((void**)&gates, g_gates);
    cudaGetSymbolAddress((void**)&Wrw,   g_Wrw);
    cudaGetSymbolAddress((void**)&A2,    g_A2);
    cudaGetSymbolAddress((void**)&rw,    g_rw);
    cudaGetSymbolAddress((void**)&Wo,    g_Wo);
    cudaGetSymbolAddress((void**)&h32,   g_h32);

    // 1. weight packing + input concat + bias-init of accumulators
    prep_all<<<(Bb * NG + 255) / 256, 256>>>(
        (const float4*)W_ih, (const float4*)W_hh, b_ih, b_hh,
        (const float4*)W_r, b_r, (const float4*)W_w, b_w,
        (const float4*)x, (const float4*)prev_read, (const float4*)h,
        (const float4*)W_o, b_o, o_out);
    // 2. gates GEMM  [256,832] x [2048,832]^T  split-K=4 (Ksub=208, 4 rounds)
    gemm_tf32<<<dim3(NG / 64, Bb / 64, 4), 256>>>(A1, Wg, gates, Bb, NG, KG, KG / 4);
    // 3. LSTM pointwise -> h_new, c_new (+ rounded h copy)
    lstm_pw<<<(Bb * CS + 255) / 256, 256>>>(c, o_h, o_c);
    // 4. addressing GEMM  h_new x [268,512]^T  split-K=8 (Ksub=64, 1 round)
    gemm_tf32<<<dim3((NRW + 63) / 64, Bb / 64, 8), 256>>>(h32, Wrw, rw, Bb, NRW, CS, CS / 8);
    // 5. fused sim + addressing + update + read_vec + A2 concat
    fused_mem<<<Bb, 512>>>(memory, read_w, write_w, o_mem, o_wr, o_ww, o_rv);
    // 6. output GEMM  split-K=9 (Ksub=64, 1 round) -> 144 CTAs
    gemm_tf32<<<dim3(256 / 64, Bb / 64, 9), 256>>>(A2, Wo, o_out, Bb, 256, KO, KO / 9);
}

// round 17
// speedup vs baseline: 1.0092x; 1.0092x over previous
#include <cuda_runtime.h>
#include <cstdint>
#include <cstddef>

// ---------------------------------------------------------------------------
// NTM single step.  B=256, N=2048, M=64, CS=512, INP=256, OUT=256
// GEMMs gather directly from source tensors (per-16-tile source select) and
// round to tf32 at fragment load — no operand packing at all.
// ---------------------------------------------------------------------------

#define Bb 256
#define Nn 2048
#define Mm 64
#define CS 512
#define KG 832      // INP + M + CS
#define NG 2048     // 4*CS
#define NRW 268     // ADDR_R(70) + ADDR_W(198)
#define KO 576      // CS + M

// output offsets (elements)
#define OFF_OUT 0
#define OFF_MEM 65536
#define OFF_H   33619968
#define OFF_C   33751040
#define OFF_WR  33882112
#define OFF_WW  34406400
#define OFF_RV  34930688

// scratch
__device__ float g_gates[Bb * NG];
__device__ float g_rw[Bb * NRW];

__device__ __forceinline__ float sigm(float x) { return 1.f / (1.f + __expf(-x)); }
__device__ __forceinline__ float ftanh(float x) {
    float e = __expf(2.f * x);
    return (e - 1.f) / (e + 1.f);
}
__device__ __forceinline__ float softplus(float x) { return x > 20.f ? x : log1pf(expf(x)); }
__device__ __forceinline__ float to_tf32(float x) {
    float r; asm("cvt.rna.tf32.f32 %0, %1;" : "=f"(r) : "f"(x)); return r;
}
__device__ __forceinline__ uint32_t f2tf(float v) {
    return __float_as_uint(to_tf32(v));
}

// ------------------------- bias init (accumulators) --------------------------

__global__ void prep_bias(const float* __restrict__ bih, const float* __restrict__ bhh,
                          const float* __restrict__ br,  const float* __restrict__ bw,
                          const float* __restrict__ bo,  float* __restrict__ o_out) {
    int idx = blockIdx.x * blockDim.x + threadIdx.x;
    if (idx < Bb * NG) {
        int j = idx & (NG - 1);
        g_gates[idx] = bih[j] + bhh[j];
    }
    if (idx < Bb * NRW) {
        int j = idx % NRW;
        g_rw[idx] = (j < 70) ? br[j] : bw[j - 70];
    }
    if (idx < Bb * 256) {
        o_out[idx] = bo[idx & 255];
    }
}

// ------------------------- tf32 GEMM, direct-source gather, split-K ----------
// C += A[M,K] @ W[N,K]^T over [z*Ksub,(z+1)*Ksub), atomic epilogue; C has bias.
// MODE 0 (gates): A = [x | prev_read | h]   (k<256 | k<320 | rest)
//                 W = [Wih | Whh]           (k<320 | rest)
// MODE 1 (addr):  A = h_new;  W rows = [Wr | Ww]  (n<70 | rest), N=268 guarded
// MODE 2 (out):   A = [h_new | read_vec]    (k<512 | rest);  W = Wo
// Rounds of up to 4 K-tiles, one commit+wait per round.  cvt.rna at frag load.

#define STAGE_BYTES 5120   // 64*20*4

__device__ __forceinline__ void mma_tf32(float* c, const uint32_t* a,
                                         uint32_t b0, uint32_t b1) {
    asm volatile(
        "mma.sync.aligned.m16n8k8.row.col.f32.tf32.tf32.f32 "
        "{%0,%1,%2,%3}, {%4,%5,%6,%7}, {%8,%9}, {%0,%1,%2,%3};\n"
        : "+f"(c[0]), "+f"(c[1]), "+f"(c[2]), "+f"(c[3])
        : "r"(a[0]), "r"(a[1]), "r"(a[2]), "r"(a[3]), "r"(b0), "r"(b1));
}

__device__ __forceinline__ void cp16(uint32_t dst, const float* src, int sz) {
    asm volatile("cp.async.ca.shared.global [%0], [%1], 16, %2;\n"
                 :: "r"(dst), "l"(src), "r"(sz));
}

template <int MODE>
__device__ __forceinline__ const float* a_src(const float* Aa, const float* Ab,
                                              const float* Ac, int row, int k0) {
    if (MODE == 0) {
        if (k0 < 256) return Aa + (size_t)row * 256 + k0;            // x
        if (k0 < 320) return Ab + (size_t)row * 64 + (k0 - 256);     // prev_read
        return Ac + (size_t)row * 512 + (k0 - 320);                  // h
    } else if (MODE == 1) {
        return Aa + (size_t)row * 512 + k0;                          // h_new
    } else {
        if (k0 < 512) return Aa + (size_t)row * 512 + k0;            // h_new
        return Ab + (size_t)row * 64 + (k0 - 512);                   // read_vec
    }
}

template <int MODE>
__device__ __forceinline__ const float* w_src(const float* Wa, const float* Wb,
                                              int row, int k0) {
    if (MODE == 0) {
        if (k0 < 320) return Wa + (size_t)row * 320 + k0;            // Wih
        return Wb + (size_t)row * 512 + (k0 - 320);                  // Whh
    } else if (MODE == 1) {
        if (row < 70) return Wa + (size_t)row * 512 + k0;            // Wr
        return Wb + (size_t)(row - 70) * 512 + k0;                   // Ww
    } else {
        return Wa + (size_t)row * 576 + k0;                          // Wo
    }
}

template <int MODE>
__global__ void __launch_bounds__(256, 2)
gemm_ntm(const float* __restrict__ Aa, const float* __restrict__ Ab,
         const float* __restrict__ Ac, const float* __restrict__ Wa,
         const float* __restrict__ Wb, float* __restrict__ C,
         int N, int Ksub) {
    __shared__ float As[4][64][20];
    __shared__ float Bs[4][64][20];
    int bm = blockIdx.y * 64, bn = blockIdx.x * 64;
    int kOff = blockIdx.z * Ksub;
    int tid = threadIdx.x;
    int wid = tid >> 5, lane = tid & 31;
    int wm = (wid & 1) * 32, wn = (wid >> 1) * 16;
    int gid = lane >> 2, tig = lane & 3;

    int r = tid >> 2;            // 0..63
    int c4 = (tid & 3) << 2;     // 0,4,8,12
    int arow = bm + r;
    int wrow = bn + r;
    bool wvalid = wrow < N;
    int wsz = wvalid ? 16 : 0;
    int wrowc = wvalid ? wrow : 0;

    uint32_t aDst = (uint32_t)__cvta_generic_to_shared(&As[0][r][c4]);
    uint32_t bDst = (uint32_t)__cvta_generic_to_shared(&Bs[0][r][c4]);

    float acc[2][2][4];
#pragma unroll
    for (int i = 0; i < 2; i++)
#pragma unroll
        for (int j = 0; j < 2; j++)
#pragma unroll
            for (int q = 0; q < 4; q++) acc[i][j][q] = 0.f;

    int numK = Ksub >> 4;

    for (int base = 0; base < numK; base += 4) {
        int cnt = (numK - base < 4) ? (numK - base) : 4;
#pragma unroll
        for (int s = 0; s < 4; s++) {
            if (s < cnt) {
                int k0 = kOff + (base + s) * 16;
                cp16(aDst + s * STAGE_BYTES, a_src<MODE>(Aa, Ab, Ac, arow, k0) + c4, 16);
                cp16(bDst + s * STAGE_BYTES, w_src<MODE>(Wa, Wb, wrowc, k0) + c4, wsz);
            }
        }
        asm volatile("cp.async.commit_group;\n");
        asm volatile("cp.async.wait_group 0;\n");
        __syncthreads();

#pragma unroll
        for (int st = 0; st < 4; st++) {
            if (st >= cnt) break;
#pragma unroll
            for (int kk = 0; kk < 16; kk += 8) {
                uint32_t af[2][4];
#pragma unroll
                for (int i = 0; i < 2; i++) {
                    int r0 = wm + i * 16 + gid;
                    af[i][0] = f2tf(As[st][r0][kk + tig]);
                    af[i][1] = f2tf(As[st][r0 + 8][kk + tig]);
                    af[i][2] = f2tf(As[st][r0][kk + tig + 4]);
                    af[i][3] = f2tf(As[st][r0 + 8][kk + tig + 4]);
                }
#pragma unroll
                for (int j = 0; j < 2; j++) {
                    int c0 = wn + j * 8 + gid;
                    uint32_t b0 = f2tf(Bs[st][c0][kk + tig]);
                    uint32_t b1 = f2tf(Bs[st][c0][kk + tig + 4]);
#pragma unroll
                    for (int i = 0; i < 2; i++) mma_tf32(acc[i][j], af[i], b0, b1);
                }
            }
        }
        __syncthreads();
    }

#pragma unroll
    for (int i = 0; i < 2; i++) {
        int row = bm + wm + i * 16 + gid;
#pragma unroll
        for (int j = 0; j < 2; j++) {
            int col = bn + wn + j * 8 + tig * 2;
            if (col < N) {
                atomicAdd(&C[(size_t)row * N + col],           acc[i][j][0]);
                atomicAdd(&C[(size_t)row * N + col + 1],       acc[i][j][1]);
                atomicAdd(&C[(size_t)(row + 8) * N + col],     acc[i][j][2]);
                atomicAdd(&C[(size_t)(row + 8) * N + col + 1], acc[i][j][3]);
            }
        }
    }
}

// ------------------------- LSTM pointwise ------------------------------------

__global__ void lstm_pw(const float* __restrict__ c_in,
                        float* __restrict__ h_out, float* __restrict__ c_out) {
    int idx = blockIdx.x * blockDim.x + threadIdx.x;
    if (idx >= Bb * CS) return;
    int b = idx >> 9, j = idx & 511;
    const float* g = g_gates + (size_t)b * NG;
    float ig = sigm(g[j]);
    float fg = sigm(g[512 + j]);
    float gg = ftanh(g[1024 + j]);
    float og = sigm(g[1536 + j]);
    float cn = fg * c_in[idx] + ig * gg;
    float hn = og * ftanh(cn);
    c_out[idx] = cn;
    h_out[idx] = hn;
}

// ------------------------- block reductions (512 threads, 16 warps) ----------

__device__ __forceinline__ float bred_max(float v, float* s16) {
#pragma unroll
    for (int off = 16; off; off >>= 1)
        v = fmaxf(v, __shfl_xor_sync(0xffffffffu, v, off));
    int wid = threadIdx.x >> 5, lane = threadIdx.x & 31;
    if (lane == 0) s16[wid] = v;
    __syncthreads();
    if (wid == 0) {
        float x = (lane < 16) ? s16[lane] : -1e30f;
#pragma unroll
        for (int off = 8; off; off >>= 1)
            x = fmaxf(x, __shfl_xor_sync(0xffffffffu, x, off));
        if (lane == 0) s16[0] = x;
    }
    __syncthreads();
    float r = s16[0];
    __syncthreads();
    return r;
}

__device__ __forceinline__ float bred_sum(float v, float* s16) {
#pragma unroll
    for (int off = 16; off; off >>= 1)
        v += __shfl_xor_sync(0xffffffffu, v, off);
    int wid = threadIdx.x >> 5, lane = threadIdx.x & 31;
    if (lane == 0) s16[wid] = v;
    __syncthreads();
    if (wid == 0) {
        float x = (lane < 16) ? s16[lane] : 0.f;
#pragma unroll
        for (int off = 8; off; off >>= 1)
            x += __shfl_xor_sync(0xffffffffu, x, off);
        if (lane == 0) s16[0] = x;
    }
    __syncthreads();
    float r = s16[0];
    __syncthreads();
    return r;
}

// ------------------------- fused memory pass ---------------------------------
// One CTA per batch element (grid=256, block=512).

__global__ void __launch_bounds__(512, 2)
fused_mem(const float* __restrict__ mem,
          const float* __restrict__ read_w_prev,
          const float* __restrict__ write_w_prev,
          float* __restrict__ mem_out,
          float* __restrict__ w_read_out,
          float* __restrict__ w_write_out,
          float* __restrict__ read_vec) {
    __shared__ float s_simr[Nn], s_simw[Nn], s_wg[Nn];
    __shared__ float s_kr[64], s_kw[64], s_er[64], s_ad[64];
    __shared__ float s_par[2][6];
    __shared__ float s_nrm[2];
    __shared__ float s_red[16];

    int b = blockIdx.x;
    int t = threadIdx.x;
    const float* base = g_rw + (size_t)b * NRW;

    if (t < 64)        s_kr[t] = base[t];
    else if (t < 128)  s_kw[t - 64] = base[70 + (t - 64)];
    else if (t < 192)  s_er[t - 128] = sigm(base[140 + (t - 128)]);
    else if (t < 256)  s_ad[t - 192] = base[204 + (t - 192)];
    else if (t < 258) {
        int head = t - 256;
        const float* ov = base + head * 70;
        float beta = softplus(ov[64]);
        float gg = sigm(ov[65]);
        float s0 = ov[66], s1 = ov[67], s2 = ov[68];
        float sm = fmaxf(s0, fmaxf(s1, s2));
        float e0 = __expf(s0 - sm), e1 = __expf(s1 - sm), e2 = __expf(s2 - sm);
        float es = e0 + e1 + e2;
        s_par[head][0] = beta; s_par[head][1] = gg;
        s_par[head][2] = e0 / es; s_par[head][3] = e1 / es; s_par[head][4] = e2 / es;
        s_par[head][5] = 1.f + softplus(ov[69]);
    }
    __syncthreads();

    int wid = t >> 5, lane = t & 31;
    if (wid < 2) {
        const float* k = wid ? s_kw : s_kr;
        float s = k[lane] * k[lane] + k[lane + 32] * k[lane + 32];
#pragma unroll
        for (int off = 16; off; off >>= 1) s += __shfl_xor_sync(0xffffffffu, s, off);
        if (lane == 0) s_nrm[wid] = sqrtf(s) + 1e-8f;
    }
    __syncthreads();

    int g = t >> 3, l = t & 7;
    float krf[8], kwf[8], erf[8], adf[8];
#pragma unroll
    for (int j = 0; j < 8; j++) {
        krf[j] = s_kr[l * 8 + j]; kwf[j] = s_kw[l * 8 + j];
        erf[j] = s_er[l * 8 + j]; adf[j] = s_ad[l * 8 + j];
    }
    float nrmr = s_nrm[0], nrmw = s_nrm[1];

    const float* mrow = mem + ((size_t)b * Nn) * 64 + l * 8;

    // pass 1: similarity
#pragma unroll 4
    for (int i = 0; i < 32; i++) {
        int n = i * 64 + g;
        const float* p = mrow + (size_t)n * 64;
        float4 m0 = *(const float4*)p;
        float4 m1 = *(const float4*)(p + 4);
        float m[8] = {m0.x, m0.y, m0.z, m0.w, m1.x, m1.y, m1.z, m1.w};
        float dr = 0.f, dw = 0.f, sq = 0.f;
#pragma unroll
        for (int j = 0; j < 8; j++) {
            dr += m[j] * krf[j]; dw += m[j] * kwf[j]; sq += m[j] * m[j];
        }
#pragma unroll
        for (int off = 4; off; off >>= 1) {
            dr += __shfl_xor_sync(0xffffffffu, dr, off);
            dw += __shfl_xor_sync(0xffffffffu, dw, off);
            sq += __shfl_xor_sync(0xffffffffu, sq, off);
        }
        if (l == 0) {
            float nm = sqrtf(sq) + 1e-8f;
            s_simr[n] = dr / (nrmr * nm);
            s_simw[n] = dw / (nrmw * nm);
        }
    }
    __syncthreads();

    // phase 2: addressing, both heads
    for (int head = 0; head < 2; head++) {
        float* sim = head ? s_simw : s_simr;
        const float* prevg = (head ? write_w_prev : read_w_prev) + (size_t)b * Nn;
        float* wout = (head ? w_write_out : w_read_out) + (size_t)b * Nn;
        float beta = s_par[head][0], gg = s_par[head][1];
        float e0 = s_par[head][2], e1 = s_par[head][3], e2 = s_par[head][4];
        float gamma = s_par[head][5];

        float loc[4];
        float mx = -1e30f;
#pragma unroll
        for (int i = 0; i < 4; i++) {
            float v = beta * sim[t + i * 512];
            loc[i] = v;
            mx = fmaxf(mx, v);
        }
        mx = bred_max(mx, s_red);
        float sum = 0.f;
#pragma unroll
        for (int i = 0; i < 4; i++) { loc[i] = __expf(loc[i] - mx); sum += loc[i]; }
        sum = bred_sum(sum, s_red);
        float inv = 1.f / sum;
#pragma unroll
        for (int i = 0; i < 4; i++) {
            int n = t + i * 512;
            s_wg[n] = gg * loc[i] * inv + (1.f - gg) * prevg[n];
        }
        __syncthreads();
        float ws[4];
        float sum2 = 0.f;
#pragma unroll
        for (int i = 0; i < 4; i++) {
            int n = t + i * 512;
            float v = e0 * s_wg[(n + Nn - 1) & (Nn - 1)] + e1 * s_wg[n]
                    + e2 * s_wg[(n + 1) & (Nn - 1)];
            v = __powf(v, gamma);
            ws[i] = v;
            sum2 += v;
        }
        sum2 = bred_sum(sum2, s_red);
        float inv2 = 1.f / (sum2 + 1e-8f);
#pragma unroll
        for (int i = 0; i < 4; i++) {
            int n = t + i * 512;
            float w = ws[i] * inv2;
            wout[n] = w;
            sim[n] = w;
        }
        __syncthreads();
    }

    // pass 3: memory update + read_vec (reverse order, streaming hints)
    float rv[8];
#pragma unroll
    for (int j = 0; j < 8; j++) rv[j] = 0.f;
    float* orow = mem_out + ((size_t)b * Nn) * 64 + l * 8;
#pragma unroll 4
    for (int i = 31; i >= 0; i--) {
        int n = i * 64 + g;
        float wr = s_simr[n], ww = s_simw[n];
        const float* p = mrow + (size_t)n * 64;
        float4 m0 = __ldcs((const float4*)p);
        float4 m1 = __ldcs((const float4*)(p + 4));
        float m[8] = {m0.x, m0.y, m0.z, m0.w, m1.x, m1.y, m1.z, m1.w};
        float o[8];
#pragma unroll
        for (int j = 0; j < 8; j++) {
            o[j] = m[j] * (1.f - ww * erf[j]) + ww * adf[j];
            rv[j] += wr * m[j];
        }
        float* q = orow + (size_t)n * 64;
        __stcs((float4*)q,       make_float4(o[0], o[1], o[2], o[3]));
        __stcs((float4*)(q + 4), make_float4(o[4], o[5], o[6], o[7]));
    }
    __syncthreads();

    float* part = (g < 32) ? &s_simr[g * 64] : &s_simw[(g - 32) * 64];
#pragma unroll
    for (int j = 0; j < 8; j++) part[l * 8 + j] = rv[j];
    __syncthreads();
    if (t < 64) {
        float s = 0.f;
#pragma unroll 8
        for (int g2 = 0; g2 < 32; g2++) s += s_simr[g2 * 64 + t];
#pragma unroll 8
        for (int g2 = 0; g2 < 32; g2++) s += s_simw[g2 * 64 + t];
        read_vec[(size_t)b * Mm + t] = s;
    }
}

// ---------------------------------------------------------------------------

extern "C" void kernel_launch(void* const* d_in, const int* in_sizes, int n_in,
                              void* d_out, int out_size) {
    const float* x         = (const float*)d_in[0];
    const float* memory    = (const float*)d_in[1];
    const float* h         = (const float*)d_in[2];
    const float* c         = (const float*)d_in[3];
    const float* read_w    = (const float*)d_in[4];
    const float* write_w   = (const float*)d_in[5];
    const float* prev_read = (const float*)d_in[6];
    const float* W_ih      = (const float*)d_in[7];
    const float* W_hh      = (const float*)d_in[8];
    const float* b_ih      = (const float*)d_in[9];
    const float* b_hh      = (const float*)d_in[10];
    const float* W_r       = (const float*)d_in[11];
    const float* b_r       = (const float*)d_in[12];
    const float* W_w       = (const float*)d_in[13];
    const float* b_w       = (const float*)d_in[14];
    const float* W_o       = (const float*)d_in[15];
    const float* b_o       = (const float*)d_in[16];

    float* out  = (float*)d_out;
    float* o_out = out + OFF_OUT;
    float* o_mem = out + OFF_MEM;
    float* o_h   = out + OFF_H;
    float* o_c   = out + OFF_C;
    float* o_wr  = out + OFF_WR;
    float* o_ww  = out + OFF_WW;
    float* o_rv  = out + OFF_RV;

    float *gates, *rw;
    cudaGetSymbolAddress((void**)&gates, g_gates);
    cudaGetSymbolAddress((void**)&rw,    g_rw);

    // 1. bias-init of the three accumulators (only remaining prep)
    prep_bias<<<(Bb * NG + 255) / 256, 256>>>(b_ih, b_hh, b_r, b_w, b_o, o_out);
    // 2. gates GEMM  [256,832]x[2048,832]^T  direct from x/prev_read/h + Wih/Whh
    gemm_ntm<0><<<dim3(NG / 64, Bb / 64, 4), 256>>>(
        x, prev_read, h, W_ih, W_hh, gates, NG, KG / 4);
    // 3. LSTM pointwise -> h_new, c_new
    lstm_pw<<<(Bb * CS + 255) / 256, 256>>>(c, o_h, o_c);
    // 4. addressing GEMM  h_new x [268,512]^T  direct from o_h + Wr/Ww
    gemm_ntm<1><<<dim3((NRW + 63) / 64, Bb / 64, 8), 256>>>(
        o_h, nullptr, nullptr, W_r, W_w, rw, NRW, CS / 8);
    // 5. fused sim + addressing + update + read_vec
    fused_mem<<<Bb, 512>>>(memory, read_w, write_w, o_mem, o_wr, o_ww, o_rv);
    // 6. output GEMM  [h_new|read_vec] x [256,576]^T  direct from o_h/o_rv + Wo
    gemm_ntm<2><<<dim3(256 / 64, Bb / 64, 9), 256>>>(
        o_h, o_rv, nullptr, W_o, nullptr, o_out, 256, KO / 9);
}